// round 7
// baseline (speedup 1.0000x reference)
#include <cuda_runtime.h>
#include <cstdint>
#include <cub/cub.cuh>

#define NUM_A 9
#define HH 128
#define WW 128
#define NBOX (NUM_A * HH * WW)   /* 147456 */
#define KTOP 6000
#define NPOST 300
#define NWIN 188                 /* ceil(6000/32) */
#define PADK 6016
#define PADC 6016
#define PT 256
#define FULLM 0xFFFFFFFFu

__constant__ float c_sizes[NUM_A] = {4.f, 8.f, 12.f, 16.f, 24.f, 32.f, 48.f, 64.f, 96.f};

__device__ unsigned g_sk_a[NBOX], g_sk_b[NBOX], g_sv_a[NBOX], g_sv_b[NBOX];
__device__ unsigned g_yk_a[KTOP], g_yk_b[KTOP], g_yv_a[KTOP], g_yv_b[KTOP];
__device__ float4 g_props[KTOP];
__device__ __align__(256) unsigned char g_cub_temp[32u * 1024u * 1024u];
__device__ float4   g_box[PADK];
__device__ float    g_area[PADK];
__device__ int      g_J1[PADK];
__device__ unsigned g_BMT[NWIN * PADC];   /* ~4.3MB kill bitmap, victim-word major */

// ---------------- decode (bit-exact vs reference) ----------------
__device__ __forceinline__ float4 decode_box(int idx, const float4* __restrict__ deltas,
                                             bool* keep)
{
    int a   = idx / (HH * WW);
    int rem = idx - a * (HH * WW);
    int h   = rem >> 7;
    int w   = rem & 127;
    float s    = c_sizes[a];
    float half = s * 0.5f;
    float ax = ((float)h + 0.5f) - half;
    float ay = ((float)w + 0.5f) - half;
    float4 d = deltas[idx];
    float x1 = fmaxf(ax + d.x, 0.0f);
    float y1 = fmaxf(ay + d.y, 0.0f);
    float bw = fmaxf(s + d.z, 0.0f);
    float bh = fmaxf(s + d.w, 0.0f);
    float x2 = x1 + bw;
    float y2 = y1 + bh;
    x1 = fminf(x1, 128.0f);
    y1 = fminf(y1, 128.0f);
    x2 = fminf(x2, 128.0f);
    y2 = fminf(y2, 128.0f);
    float ow = x2 - x1;
    float oh = y2 - y1;
    *keep = (ow >= 3.0f) && (oh >= 3.0f);
    return make_float4(x1, y1, ow, oh);
}

// exact: rn(n/ar) >= 0.7f, division-free common path
__device__ __forceinline__ bool iou_ge(float n, float ar)
{
    float t = fmaf(-0.7f, ar, n);
    if (t >= 0.0f) return true;
    if (t <= -3.2e-8f * ar) return false;
    return __fdiv_rn(n, ar) >= 0.7f;
}

__global__ void k_score(const float* __restrict__ scores, const float4* __restrict__ deltas)
{
    int i = blockIdx.x * blockDim.x + threadIdx.x;
    if (i >= NBOX) return;
    bool keep;
    (void)decode_box(i, deltas, &keep);
    float sc = keep ? scores[i] : __int_as_float(0xFF800000);
    unsigned u   = __float_as_uint(sc);
    unsigned asc = u ^ ((unsigned)((int)u >> 31) | 0x80000000u);
    g_sk_a[i] = ~asc;
    g_sv_a[i] = (unsigned)i;
}

__global__ void k_props(const float4* __restrict__ deltas)
{
    int r = blockIdx.x * blockDim.x + threadIdx.x;
    if (r >= KTOP) return;
    int idx = (int)g_sv_b[r];
    bool keep;
    float4 p = decode_box(idx, deltas, &keep);
    g_props[r] = p;
    float y2 = p.y + p.w;
    g_yk_a[r] = ~__float_as_uint(y2);
    g_yv_a[r] = (unsigned)r;
}

__global__ void k_zero()
{
    int i = blockIdx.x * blockDim.x + threadIdx.x;
    if (i < NWIN * PADC) g_BMT[i] = 0u;
}

// boxes in y2-order, areas, exact J1 band bound
__global__ void k_prep()
{
    int m = blockIdx.x * blockDim.x + threadIdx.x;
    if (m >= PADK) return;
    if (m < KTOP) {
        float4 p = g_props[(int)g_yv_b[m]];
        float x1 = p.x, y1 = p.y, x2 = p.x + p.z, y2 = p.y + p.w;
        g_box[m]  = make_float4(x1, y1, x2, y2);
        g_area[m] = fmaxf((x2 - x1) * (y2 - y1), 1e-6f);
        // first j>m with fl(y2_j - y1_m) <= -1 -> ih_fl <= 0 beyond (exact, monotone)
        int lo = m + 1, hi = KTOP;
        while (lo < hi) {
            int mid = (lo + hi) >> 1;
            float y2j = __uint_as_float(~g_yk_b[mid]);
            if (__fadd_rn(y2j, -y1) <= -1.0f) hi = mid; else lo = mid + 1;
        }
        g_J1[m] = lo;
    } else {
        g_box[m] = make_float4(0.f, 0.f, 0.f, 0.f);
        g_area[m] = 1.f;
        g_J1[m] = 0;
    }
}

// pair enumeration: CTA owns 32 i's; tiles j-band through shared; fills BMT
__global__ void __launch_bounds__(256) void_guard();  // (no-op decl to keep nvcc happy if unused)
__global__ void __launch_bounds__(256) k_pairs()
{
    __shared__ float4 tb[PT];
    __shared__ float  ta[PT];
    __shared__ int sMax;
    int tid = threadIdx.x;
    int i0  = blockIdx.x * 32;
    int il  = tid >> 3, ck = tid & 7;
    int i   = i0 + il;
    bool iok = (i < KTOP);
    float4 bi = iok ? g_box[i] : make_float4(0.f, 0.f, 0.f, 0.f);
    float  ai = iok ? g_area[i] : 1.f;
    int   J1i = iok ? g_J1[i] : 0;
    if (tid == 0) sMax = 0;
    __syncthreads();
    if (ck == 0 && iok) atomicMax(&sMax, J1i);
    __syncthreads();
    int jend = sMax;
    int t0 = (i0 + 1) & ~31;
    for (int t = t0; t < jend; t += PT) {
        __syncthreads();
        {
            int idx = t + tid;
            if (idx < PADK) { tb[tid] = g_box[idx]; ta[tid] = g_area[idx]; }
            else            { tb[tid] = make_float4(0.f,0.f,0.f,0.f); ta[tid] = 1.f; }
        }
        __syncthreads();
        if (!iok) continue;
        int jbase = t + (ck << 5);
        unsigned fwd = 0;
        for (int b = 0; b < 32; ++b) {
            int j = jbase + b;
            if (j <= i || j >= J1i) continue;
            float4 bj = tb[(ck << 5) + b];
            float iw = fminf(bi.z, bj.z) - fmaxf(bi.x, bj.x) + 1.0f;
            if (iw <= 0.0f) continue;
            float ih = fminf(bi.w, bj.w) - fmaxf(bi.y, bj.y) + 1.0f;
            if (ih <= 0.0f) continue;
            float inter = iw * ih;
            if (iou_ge(inter, ta[(ck << 5) + b])) fwd |= 1u << b;  // i kills j
            if (iou_ge(inter, ai))                                  // j kills i
                atomicOr(&g_BMT[(unsigned)(i >> 5) * PADC + j], 1u << (i & 31));
        }
        if (fwd) atomicOr(&g_BMT[(unsigned)(jbase >> 5) * PADC + i], fwd);
    }
}

// serial chain: pure bitops, prefetched BMT columns, 2 barriers/window
__global__ void __launch_bounds__(1024, 1) k_serial(float* __restrict__ out)
{
    __shared__ unsigned valid[NWIN];
    __shared__ unsigned s_exec;
    __shared__ int ssc[1024];
    const int tid  = threadIdx.x;
    const int lane = tid & 31;
    const int wid  = tid >> 5;

    for (int i = tid; i < NPOST * 4; i += 1024) out[i] = 0.0f;
    if (tid < NWIN) valid[tid] = (tid == NWIN - 1) ? 0x0000FFFFu : FULLM;

    unsigned cur[7], nxt[7];
    if (wid == 31) {
        nxt[0] = g_BMT[0 * PADC + lane];            // u=0, c=lane (window 0)
    } else {
#pragma unroll
        for (int k = 0; k < 7; ++k) {
            int u = wid + 31 * k;
            nxt[k] = (u < NWIN) ? g_BMT[(unsigned)u * PADC + lane] : 0u;
        }
    }

    for (int w = 0; w < NWIN; ++w) {
        __syncthreads();                            // A: prior applies visible
        unsigned vm = valid[w];
#pragma unroll
        for (int k = 0; k < 7; ++k) cur[k] = nxt[k];
        int wn = w + 1;
        if (wn < NWIN) {                            // prefetch next window's columns
            unsigned cbase = (unsigned)(wn << 5) + lane;
            if (wid == 31) {
                nxt[0] = g_BMT[(unsigned)wn * PADC + cbase];
            } else {
#pragma unroll
                for (int k = 0; k < 7; ++k) {
                    int u = wid + 31 * k;
                    nxt[k] = (u < NWIN) ? g_BMT[(unsigned)u * PADC + cbase] : 0u;
                }
            }
        }
        if (vm == 0) continue;                      // uniform

        if (wid == 31) {
            // forward-only row for chain resolve
            unsigned row = (lane < 31) ? (cur[0] & (0xFFFFFFFEu << lane)) : 0u;
            unsigned exec;
            if (__ballot_sync(FULLM, row != 0u) == 0u) {
                exec = vm;                          // no intra-window edges
            } else {
                unsigned rem = 0; exec = 0;
#pragma unroll
                for (int l = 0; l < 32; ++l) {
                    unsigned rl = __shfl_sync(FULLM, row, l);
                    unsigned b = 1u << l;
                    if ((vm & b) && !(rem & b)) { exec |= b; rem |= rl; }
                }
            }
            if (lane == 0) s_exec = exec;
        }
        __syncthreads();                            // B: exec published

        if (wid < 31) {
            unsigned exec = s_exec;
#pragma unroll
            for (int k = 0; k < 7; ++k) {
                unsigned d = ((exec >> lane) & 1u) ? cur[k] : 0u;
#pragma unroll
                for (int o = 16; o; o >>= 1) d |= __shfl_xor_sync(FULLM, d, o);
                int u = wid + 31 * k;
                if (lane == 0 && u < NWIN && d) valid[u] &= ~d;
            }
        }
    }
    __syncthreads();

    // output: first NPOST survivors in y-order
    int c = (tid < NWIN) ? __popc(valid[tid]) : 0;
    ssc[tid] = c;
    __syncthreads();
    for (int off = 1; off < 1024; off <<= 1) {
        int add = (tid >= off) ? ssc[tid - off] : 0;
        __syncthreads();
        ssc[tid] += add;
        __syncthreads();
    }
    if (tid < NWIN) {
        int pos = ssc[tid] - c;
        unsigned v = valid[tid];
        while (v) {
            int b = __ffs(v) - 1; v &= v - 1;
            if (pos < NPOST) {
                int m = (tid << 5) + b;
                float4 p = g_props[(int)g_yv_b[m]];
                out[pos * 4 + 0] = p.x;
                out[pos * 4 + 1] = p.y;
                out[pos * 4 + 2] = p.z;
                out[pos * 4 + 3] = p.w;
            }
            ++pos;
        }
    }
}

extern "C" void kernel_launch(void* const* d_in, const int* in_sizes, int n_in,
                              void* d_out, int out_size)
{
    const float*  scores = (const float*)d_in[0];
    const float4* deltas = (const float4*)d_in[1];
    float* out = (float*)d_out;
    (void)in_sizes; (void)n_in; (void)out_size;

    void *p_ska, *p_skb, *p_sva, *p_svb, *p_yka, *p_ykb, *p_yva, *p_yvb, *p_tmp;
    cudaGetSymbolAddress(&p_ska, g_sk_a);
    cudaGetSymbolAddress(&p_skb, g_sk_b);
    cudaGetSymbolAddress(&p_sva, g_sv_a);
    cudaGetSymbolAddress(&p_svb, g_sv_b);
    cudaGetSymbolAddress(&p_yka, g_yk_a);
    cudaGetSymbolAddress(&p_ykb, g_yk_b);
    cudaGetSymbolAddress(&p_yva, g_yv_a);
    cudaGetSymbolAddress(&p_yvb, g_yv_b);
    cudaGetSymbolAddress(&p_tmp, g_cub_temp);

    k_zero<<<(NWIN * PADC + 1023) / 1024, 1024>>>();
    k_score<<<(NBOX + 255) / 256, 256>>>(scores, deltas);

    size_t tb = sizeof(g_cub_temp);
    cub::DeviceRadixSort::SortPairs(p_tmp, tb,
        (const unsigned*)p_ska, (unsigned*)p_skb,
        (const unsigned*)p_sva, (unsigned*)p_svb, NBOX);

    k_props<<<(KTOP + 255) / 256, 256>>>(deltas);

    tb = sizeof(g_cub_temp);
    cub::DeviceRadixSort::SortPairs(p_tmp, tb,
        (const unsigned*)p_yka, (unsigned*)p_ykb,
        (const unsigned*)p_yva, (unsigned*)p_yvb, KTOP);

    k_prep<<<(PADK + 255) / 256, 256>>>();
    k_pairs<<<NWIN, 256>>>();
    k_serial<<<1, 1024>>>(out);
}

// round 8
// speedup vs baseline: 1.0032x; 1.0032x over previous
#include <cuda_runtime.h>
#include <cstdint>
#include <cub/cub.cuh>

#define NUM_A 9
#define HH 128
#define WW 128
#define NBOX (NUM_A * HH * WW)   /* 147456 */
#define KTOP 6000
#define NPOST 300
#define NWIN 188                 /* ceil(6000/32) */
#define PADK 6016
#define PADC 6016
#define PT 256
#define FULLM 0xFFFFFFFFu

__constant__ float c_sizes[NUM_A] = {4.f, 8.f, 12.f, 16.f, 24.f, 32.f, 48.f, 64.f, 96.f};

__device__ unsigned g_sk_a[NBOX], g_sk_b[NBOX], g_sv_a[NBOX], g_sv_b[NBOX];
__device__ unsigned g_yk_a[KTOP], g_yk_b[KTOP], g_yv_a[KTOP], g_yv_b[KTOP];
__device__ float4 g_props[KTOP];
__device__ __align__(256) unsigned char g_cub_temp[32u * 1024u * 1024u];
__device__ float4   g_box[PADK];
__device__ float    g_area[PADK];
__device__ int      g_J1[PADK];
__device__ unsigned g_BMT[NWIN * PADC];   /* ~4.3MB kill bitmap, victim-word major */

// ---------------- decode (bit-exact vs reference) ----------------
__device__ __forceinline__ float4 decode_box(int idx, const float4* __restrict__ deltas,
                                             bool* keep)
{
    int a   = idx / (HH * WW);
    int rem = idx - a * (HH * WW);
    int h   = rem >> 7;
    int w   = rem & 127;
    float s    = c_sizes[a];
    float half = s * 0.5f;
    float ax = ((float)h + 0.5f) - half;
    float ay = ((float)w + 0.5f) - half;
    float4 d = deltas[idx];
    float x1 = fmaxf(ax + d.x, 0.0f);
    float y1 = fmaxf(ay + d.y, 0.0f);
    float bw = fmaxf(s + d.z, 0.0f);
    float bh = fmaxf(s + d.w, 0.0f);
    float x2 = x1 + bw;
    float y2 = y1 + bh;
    x1 = fminf(x1, 128.0f);
    y1 = fminf(y1, 128.0f);
    x2 = fminf(x2, 128.0f);
    y2 = fminf(y2, 128.0f);
    float ow = x2 - x1;
    float oh = y2 - y1;
    *keep = (ow >= 3.0f) && (oh >= 3.0f);
    return make_float4(x1, y1, ow, oh);
}

// exact: rn(n/ar) >= 0.7f, division-free common path
__device__ __forceinline__ bool iou_ge(float n, float ar)
{
    float t = fmaf(-0.7f, ar, n);
    if (t >= 0.0f) return true;
    if (t <= -3.2e-8f * ar) return false;
    return __fdiv_rn(n, ar) >= 0.7f;
}

__global__ void k_score(const float* __restrict__ scores, const float4* __restrict__ deltas)
{
    int i = blockIdx.x * blockDim.x + threadIdx.x;
    if (i >= NBOX) return;
    bool keep;
    (void)decode_box(i, deltas, &keep);
    float sc = keep ? scores[i] : __int_as_float(0xFF800000);
    unsigned u   = __float_as_uint(sc);
    unsigned asc = u ^ ((unsigned)((int)u >> 31) | 0x80000000u);
    g_sk_a[i] = ~asc;
    g_sv_a[i] = (unsigned)i;
}

__global__ void k_props(const float4* __restrict__ deltas)
{
    int r = blockIdx.x * blockDim.x + threadIdx.x;
    if (r >= KTOP) return;
    int idx = (int)g_sv_b[r];
    bool keep;
    float4 p = decode_box(idx, deltas, &keep);
    g_props[r] = p;
    float y2 = p.y + p.w;
    g_yk_a[r] = ~__float_as_uint(y2);
    g_yv_a[r] = (unsigned)r;
}

__global__ void k_zero()
{
    int i = blockIdx.x * blockDim.x + threadIdx.x;
    if (i < NWIN * PADC) g_BMT[i] = 0u;
}

// boxes in y2-order, areas, exact J1 band bound
__global__ void k_prep()
{
    int m = blockIdx.x * blockDim.x + threadIdx.x;
    if (m >= PADK) return;
    if (m < KTOP) {
        float4 p = g_props[(int)g_yv_b[m]];
        float x1 = p.x, y1 = p.y, x2 = p.x + p.z, y2 = p.y + p.w;
        g_box[m]  = make_float4(x1, y1, x2, y2);
        g_area[m] = fmaxf((x2 - x1) * (y2 - y1), 1e-6f);
        // first j>m with fl(y2_j - y1_m) <= -1 -> ih_fl <= 0 beyond (exact, monotone)
        int lo = m + 1, hi = KTOP;
        while (lo < hi) {
            int mid = (lo + hi) >> 1;
            float y2j = __uint_as_float(~g_yk_b[mid]);
            if (__fadd_rn(y2j, -y1) <= -1.0f) hi = mid; else lo = mid + 1;
        }
        g_J1[m] = lo;
    } else {
        g_box[m] = make_float4(0.f, 0.f, 0.f, 0.f);
        g_area[m] = 1.f;
        g_J1[m] = 0;
    }
}

// pair enumeration: CTA owns 32 i's; tiles j-band through shared; fills BMT
__global__ void __launch_bounds__(256) void_guard();  // (no-op decl to keep nvcc happy if unused)
__global__ void __launch_bounds__(256) k_pairs()
{
    __shared__ float4 tb[PT];
    __shared__ float  ta[PT];
    __shared__ int sMax;
    int tid = threadIdx.x;
    int i0  = blockIdx.x * 32;
    int il  = tid >> 3, ck = tid & 7;
    int i   = i0 + il;
    bool iok = (i < KTOP);
    float4 bi = iok ? g_box[i] : make_float4(0.f, 0.f, 0.f, 0.f);
    float  ai = iok ? g_area[i] : 1.f;
    int   J1i = iok ? g_J1[i] : 0;
    if (tid == 0) sMax = 0;
    __syncthreads();
    if (ck == 0 && iok) atomicMax(&sMax, J1i);
    __syncthreads();
    int jend = sMax;
    int t0 = (i0 + 1) & ~31;
    for (int t = t0; t < jend; t += PT) {
        __syncthreads();
        {
            int idx = t + tid;
            if (idx < PADK) { tb[tid] = g_box[idx]; ta[tid] = g_area[idx]; }
            else            { tb[tid] = make_float4(0.f,0.f,0.f,0.f); ta[tid] = 1.f; }
        }
        __syncthreads();
        if (!iok) continue;
        int jbase = t + (ck << 5);
        unsigned fwd = 0;
        for (int b = 0; b < 32; ++b) {
            int j = jbase + b;
            if (j <= i || j >= J1i) continue;
            float4 bj = tb[(ck << 5) + b];
            float iw = fminf(bi.z, bj.z) - fmaxf(bi.x, bj.x) + 1.0f;
            if (iw <= 0.0f) continue;
            float ih = fminf(bi.w, bj.w) - fmaxf(bi.y, bj.y) + 1.0f;
            if (ih <= 0.0f) continue;
            float inter = iw * ih;
            if (iou_ge(inter, ta[(ck << 5) + b])) fwd |= 1u << b;  // i kills j
            if (iou_ge(inter, ai))                                  // j kills i
                atomicOr(&g_BMT[(unsigned)(i >> 5) * PADC + j], 1u << (i & 31));
        }
        if (fwd) atomicOr(&g_BMT[(unsigned)(jbase >> 5) * PADC + i], fwd);
    }
}

// serial chain: pure bitops, prefetched BMT columns, 2 barriers/window
__global__ void __launch_bounds__(1024, 1) k_serial(float* __restrict__ out)
{
    __shared__ unsigned valid[NWIN];
    __shared__ unsigned s_exec;
    __shared__ int ssc[1024];
    const int tid  = threadIdx.x;
    const int lane = tid & 31;
    const int wid  = tid >> 5;

    for (int i = tid; i < NPOST * 4; i += 1024) out[i] = 0.0f;
    if (tid < NWIN) valid[tid] = (tid == NWIN - 1) ? 0x0000FFFFu : FULLM;

    unsigned cur[7], nxt[7];
    if (wid == 31) {
        nxt[0] = g_BMT[0 * PADC + lane];            // u=0, c=lane (window 0)
    } else {
#pragma unroll
        for (int k = 0; k < 7; ++k) {
            int u = wid + 31 * k;
            nxt[k] = (u < NWIN) ? g_BMT[(unsigned)u * PADC + lane] : 0u;
        }
    }

    for (int w = 0; w < NWIN; ++w) {
        __syncthreads();                            // A: prior applies visible
        unsigned vm = valid[w];
#pragma unroll
        for (int k = 0; k < 7; ++k) cur[k] = nxt[k];
        int wn = w + 1;
        if (wn < NWIN) {                            // prefetch next window's columns
            unsigned cbase = (unsigned)(wn << 5) + lane;
            if (wid == 31) {
                nxt[0] = g_BMT[(unsigned)wn * PADC + cbase];
            } else {
#pragma unroll
                for (int k = 0; k < 7; ++k) {
                    int u = wid + 31 * k;
                    nxt[k] = (u < NWIN) ? g_BMT[(unsigned)u * PADC + cbase] : 0u;
                }
            }
        }
        if (vm == 0) continue;                      // uniform

        if (wid == 31) {
            // forward-only row for chain resolve
            unsigned row = (lane < 31) ? (cur[0] & (0xFFFFFFFEu << lane)) : 0u;
            unsigned exec;
            if (__ballot_sync(FULLM, row != 0u) == 0u) {
                exec = vm;                          // no intra-window edges
            } else {
                unsigned rem = 0; exec = 0;
#pragma unroll
                for (int l = 0; l < 32; ++l) {
                    unsigned rl = __shfl_sync(FULLM, row, l);
                    unsigned b = 1u << l;
                    if ((vm & b) && !(rem & b)) { exec |= b; rem |= rl; }
                }
            }
            if (lane == 0) s_exec = exec;
        }
        __syncthreads();                            // B: exec published

        if (wid < 31) {
            unsigned exec = s_exec;
#pragma unroll
            for (int k = 0; k < 7; ++k) {
                unsigned d = ((exec >> lane) & 1u) ? cur[k] : 0u;
#pragma unroll
                for (int o = 16; o; o >>= 1) d |= __shfl_xor_sync(FULLM, d, o);
                int u = wid + 31 * k;
                if (lane == 0 && u < NWIN && d) valid[u] &= ~d;
            }
        }
    }
    __syncthreads();

    // output: first NPOST survivors in y-order
    int c = (tid < NWIN) ? __popc(valid[tid]) : 0;
    ssc[tid] = c;
    __syncthreads();
    for (int off = 1; off < 1024; off <<= 1) {
        int add = (tid >= off) ? ssc[tid - off] : 0;
        __syncthreads();
        ssc[tid] += add;
        __syncthreads();
    }
    if (tid < NWIN) {
        int pos = ssc[tid] - c;
        unsigned v = valid[tid];
        while (v) {
            int b = __ffs(v) - 1; v &= v - 1;
            if (pos < NPOST) {
                int m = (tid << 5) + b;
                float4 p = g_props[(int)g_yv_b[m]];
                out[pos * 4 + 0] = p.x;
                out[pos * 4 + 1] = p.y;
                out[pos * 4 + 2] = p.z;
                out[pos * 4 + 3] = p.w;
            }
            ++pos;
        }
    }
}

extern "C" void kernel_launch(void* const* d_in, const int* in_sizes, int n_in,
                              void* d_out, int out_size)
{
    const float*  scores = (const float*)d_in[0];
    const float4* deltas = (const float4*)d_in[1];
    float* out = (float*)d_out;
    (void)in_sizes; (void)n_in; (void)out_size;

    void *p_ska, *p_skb, *p_sva, *p_svb, *p_yka, *p_ykb, *p_yva, *p_yvb, *p_tmp;
    cudaGetSymbolAddress(&p_ska, g_sk_a);
    cudaGetSymbolAddress(&p_skb, g_sk_b);
    cudaGetSymbolAddress(&p_sva, g_sv_a);
    cudaGetSymbolAddress(&p_svb, g_sv_b);
    cudaGetSymbolAddress(&p_yka, g_yk_a);
    cudaGetSymbolAddress(&p_ykb, g_yk_b);
    cudaGetSymbolAddress(&p_yva, g_yv_a);
    cudaGetSymbolAddress(&p_yvb, g_yv_b);
    cudaGetSymbolAddress(&p_tmp, g_cub_temp);

    k_zero<<<(NWIN * PADC + 1023) / 1024, 1024>>>();
    k_score<<<(NBOX + 255) / 256, 256>>>(scores, deltas);

    size_t tb = sizeof(g_cub_temp);
    cub::DeviceRadixSort::SortPairs(p_tmp, tb,
        (const unsigned*)p_ska, (unsigned*)p_skb,
        (const unsigned*)p_sva, (unsigned*)p_svb, NBOX);

    k_props<<<(KTOP + 255) / 256, 256>>>(deltas);

    tb = sizeof(g_cub_temp);
    cub::DeviceRadixSort::SortPairs(p_tmp, tb,
        (const unsigned*)p_yka, (unsigned*)p_ykb,
        (const unsigned*)p_yva, (unsigned*)p_yvb, KTOP);

    k_prep<<<(PADK + 255) / 256, 256>>>();
    k_pairs<<<NWIN, 256>>>();
    k_serial<<<1, 1024>>>(out);
}

// round 9
// speedup vs baseline: 1.0080x; 1.0048x over previous
#include <cuda_runtime.h>
#include <cstdint>
#include <cub/cub.cuh>

#define NUM_A 9
#define HH 128
#define WW 128
#define NBOX (NUM_A * HH * WW)   /* 147456 */
#define KTOP 6000
#define NPOST 300
#define NWIN 188                 /* ceil(6000/32) */
#define PADK 6016
#define PADC 6016
#define PT 256
#define FULLM 0xFFFFFFFFu

__constant__ float c_sizes[NUM_A] = {4.f, 8.f, 12.f, 16.f, 24.f, 32.f, 48.f, 64.f, 96.f};

__device__ unsigned g_sk_a[NBOX], g_sk_b[NBOX], g_sv_a[NBOX], g_sv_b[NBOX];
__device__ unsigned g_yk_a[KTOP], g_yk_b[KTOP], g_yv_a[KTOP], g_yv_b[KTOP];
__device__ float4 g_props[KTOP];
__device__ __align__(256) unsigned char g_cub_temp[32u * 1024u * 1024u];
__device__ float4   g_box[PADK];
__device__ float    g_area[PADK];
__device__ int      g_J1[PADK];
__device__ unsigned g_BMT[NWIN * PADC];   /* ~4.3MB kill bitmap, victim-word major */

// ---------------- decode (bit-exact vs reference) ----------------
__device__ __forceinline__ float4 decode_box(int idx, const float4* __restrict__ deltas,
                                             bool* keep)
{
    int a   = idx / (HH * WW);
    int rem = idx - a * (HH * WW);
    int h   = rem >> 7;
    int w   = rem & 127;
    float s    = c_sizes[a];
    float half = s * 0.5f;
    float ax = ((float)h + 0.5f) - half;
    float ay = ((float)w + 0.5f) - half;
    float4 d = deltas[idx];
    float x1 = fmaxf(ax + d.x, 0.0f);
    float y1 = fmaxf(ay + d.y, 0.0f);
    float bw = fmaxf(s + d.z, 0.0f);
    float bh = fmaxf(s + d.w, 0.0f);
    float x2 = x1 + bw;
    float y2 = y1 + bh;
    x1 = fminf(x1, 128.0f);
    y1 = fminf(y1, 128.0f);
    x2 = fminf(x2, 128.0f);
    y2 = fminf(y2, 128.0f);
    float ow = x2 - x1;
    float oh = y2 - y1;
    *keep = (ow >= 3.0f) && (oh >= 3.0f);
    return make_float4(x1, y1, ow, oh);
}

// exact: rn(n/ar) >= 0.7f, division-free common path
__device__ __forceinline__ bool iou_ge(float n, float ar)
{
    float t = fmaf(-0.7f, ar, n);
    if (t >= 0.0f) return true;
    if (t <= -3.2e-8f * ar) return false;
    return __fdiv_rn(n, ar) >= 0.7f;
}

__global__ void k_score(const float* __restrict__ scores, const float4* __restrict__ deltas)
{
    int i = blockIdx.x * blockDim.x + threadIdx.x;
    if (i >= NBOX) return;
    bool keep;
    (void)decode_box(i, deltas, &keep);
    float sc = keep ? scores[i] : __int_as_float(0xFF800000);
    unsigned u   = __float_as_uint(sc);
    unsigned asc = u ^ ((unsigned)((int)u >> 31) | 0x80000000u);
    g_sk_a[i] = ~asc;
    g_sv_a[i] = (unsigned)i;
}

__global__ void k_props(const float4* __restrict__ deltas)
{
    int r = blockIdx.x * blockDim.x + threadIdx.x;
    if (r >= KTOP) return;
    int idx = (int)g_sv_b[r];
    bool keep;
    float4 p = decode_box(idx, deltas, &keep);
    g_props[r] = p;
    float y2 = p.y + p.w;
    g_yk_a[r] = ~__float_as_uint(y2);
    g_yv_a[r] = (unsigned)r;
}

__global__ void k_zero()
{
    int i = blockIdx.x * blockDim.x + threadIdx.x;
    if (i < NWIN * PADC) g_BMT[i] = 0u;
}

// boxes in y2-order, areas, exact J1 band bound
__global__ void k_prep()
{
    int m = blockIdx.x * blockDim.x + threadIdx.x;
    if (m >= PADK) return;
    if (m < KTOP) {
        float4 p = g_props[(int)g_yv_b[m]];
        float x1 = p.x, y1 = p.y, x2 = p.x + p.z, y2 = p.y + p.w;
        g_box[m]  = make_float4(x1, y1, x2, y2);
        g_area[m] = fmaxf((x2 - x1) * (y2 - y1), 1e-6f);
        // first j>m with fl(y2_j - y1_m) <= -1 -> ih_fl <= 0 beyond (exact, monotone)
        int lo = m + 1, hi = KTOP;
        while (lo < hi) {
            int mid = (lo + hi) >> 1;
            float y2j = __uint_as_float(~g_yk_b[mid]);
            if (__fadd_rn(y2j, -y1) <= -1.0f) hi = mid; else lo = mid + 1;
        }
        g_J1[m] = lo;
    } else {
        g_box[m] = make_float4(0.f, 0.f, 0.f, 0.f);
        g_area[m] = 1.f;
        g_J1[m] = 0;
    }
}

// pair enumeration: CTA owns 32 i's; tiles j-band through shared; fills BMT
__global__ void __launch_bounds__(256) void_guard();  // (no-op decl to keep nvcc happy if unused)
__global__ void __launch_bounds__(256) k_pairs()
{
    __shared__ float4 tb[PT];
    __shared__ float  ta[PT];
    __shared__ int sMax;
    int tid = threadIdx.x;
    int i0  = blockIdx.x * 32;
    int il  = tid >> 3, ck = tid & 7;
    int i   = i0 + il;
    bool iok = (i < KTOP);
    float4 bi = iok ? g_box[i] : make_float4(0.f, 0.f, 0.f, 0.f);
    float  ai = iok ? g_area[i] : 1.f;
    int   J1i = iok ? g_J1[i] : 0;
    if (tid == 0) sMax = 0;
    __syncthreads();
    if (ck == 0 && iok) atomicMax(&sMax, J1i);
    __syncthreads();
    int jend = sMax;
    int t0 = (i0 + 1) & ~31;
    for (int t = t0; t < jend; t += PT) {
        __syncthreads();
        {
            int idx = t + tid;
            if (idx < PADK) { tb[tid] = g_box[idx]; ta[tid] = g_area[idx]; }
            else            { tb[tid] = make_float4(0.f,0.f,0.f,0.f); ta[tid] = 1.f; }
        }
        __syncthreads();
        if (!iok) continue;
        int jbase = t + (ck << 5);
        unsigned fwd = 0;
        for (int b = 0; b < 32; ++b) {
            int j = jbase + b;
            if (j <= i || j >= J1i) continue;
            float4 bj = tb[(ck << 5) + b];
            float iw = fminf(bi.z, bj.z) - fmaxf(bi.x, bj.x) + 1.0f;
            if (iw <= 0.0f) continue;
            float ih = fminf(bi.w, bj.w) - fmaxf(bi.y, bj.y) + 1.0f;
            if (ih <= 0.0f) continue;
            float inter = iw * ih;
            if (iou_ge(inter, ta[(ck << 5) + b])) fwd |= 1u << b;  // i kills j
            if (iou_ge(inter, ai))                                  // j kills i
                atomicOr(&g_BMT[(unsigned)(i >> 5) * PADC + j], 1u << (i & 31));
        }
        if (fwd) atomicOr(&g_BMT[(unsigned)(jbase >> 5) * PADC + i], fwd);
    }
}

// serial chain: pure bitops, prefetched BMT columns, 2 barriers/window
__global__ void __launch_bounds__(1024, 1) k_serial(float* __restrict__ out)
{
    __shared__ unsigned valid[NWIN];
    __shared__ unsigned s_exec;
    __shared__ int ssc[1024];
    const int tid  = threadIdx.x;
    const int lane = tid & 31;
    const int wid  = tid >> 5;

    for (int i = tid; i < NPOST * 4; i += 1024) out[i] = 0.0f;
    if (tid < NWIN) valid[tid] = (tid == NWIN - 1) ? 0x0000FFFFu : FULLM;

    unsigned cur[7], nxt[7];
    if (wid == 31) {
        nxt[0] = g_BMT[0 * PADC + lane];            // u=0, c=lane (window 0)
    } else {
#pragma unroll
        for (int k = 0; k < 7; ++k) {
            int u = wid + 31 * k;
            nxt[k] = (u < NWIN) ? g_BMT[(unsigned)u * PADC + lane] : 0u;
        }
    }

    for (int w = 0; w < NWIN; ++w) {
        __syncthreads();                            // A: prior applies visible
        unsigned vm = valid[w];
#pragma unroll
        for (int k = 0; k < 7; ++k) cur[k] = nxt[k];
        int wn = w + 1;
        if (wn < NWIN) {                            // prefetch next window's columns
            unsigned cbase = (unsigned)(wn << 5) + lane;
            if (wid == 31) {
                nxt[0] = g_BMT[(unsigned)wn * PADC + cbase];
            } else {
#pragma unroll
                for (int k = 0; k < 7; ++k) {
                    int u = wid + 31 * k;
                    nxt[k] = (u < NWIN) ? g_BMT[(unsigned)u * PADC + cbase] : 0u;
                }
            }
        }
        if (vm == 0) continue;                      // uniform

        if (wid == 31) {
            // forward-only row for chain resolve
            unsigned row = (lane < 31) ? (cur[0] & (0xFFFFFFFEu << lane)) : 0u;
            unsigned exec;
            if (__ballot_sync(FULLM, row != 0u) == 0u) {
                exec = vm;                          // no intra-window edges
            } else {
                unsigned rem = 0; exec = 0;
#pragma unroll
                for (int l = 0; l < 32; ++l) {
                    unsigned rl = __shfl_sync(FULLM, row, l);
                    unsigned b = 1u << l;
                    if ((vm & b) && !(rem & b)) { exec |= b; rem |= rl; }
                }
            }
            if (lane == 0) s_exec = exec;
        }
        __syncthreads();                            // B: exec published

        if (wid < 31) {
            unsigned exec = s_exec;
#pragma unroll
            for (int k = 0; k < 7; ++k) {
                unsigned d = ((exec >> lane) & 1u) ? cur[k] : 0u;
#pragma unroll
                for (int o = 16; o; o >>= 1) d |= __shfl_xor_sync(FULLM, d, o);
                int u = wid + 31 * k;
                if (lane == 0 && u < NWIN && d) valid[u] &= ~d;
            }
        }
    }
    __syncthreads();

    // output: first NPOST survivors in y-order
    int c = (tid < NWIN) ? __popc(valid[tid]) : 0;
    ssc[tid] = c;
    __syncthreads();
    for (int off = 1; off < 1024; off <<= 1) {
        int add = (tid >= off) ? ssc[tid - off] : 0;
        __syncthreads();
        ssc[tid] += add;
        __syncthreads();
    }
    if (tid < NWIN) {
        int pos = ssc[tid] - c;
        unsigned v = valid[tid];
        while (v) {
            int b = __ffs(v) - 1; v &= v - 1;
            if (pos < NPOST) {
                int m = (tid << 5) + b;
                float4 p = g_props[(int)g_yv_b[m]];
                out[pos * 4 + 0] = p.x;
                out[pos * 4 + 1] = p.y;
                out[pos * 4 + 2] = p.z;
                out[pos * 4 + 3] = p.w;
            }
            ++pos;
        }
    }
}

extern "C" void kernel_launch(void* const* d_in, const int* in_sizes, int n_in,
                              void* d_out, int out_size)
{
    const float*  scores = (const float*)d_in[0];
    const float4* deltas = (const float4*)d_in[1];
    float* out = (float*)d_out;
    (void)in_sizes; (void)n_in; (void)out_size;

    void *p_ska, *p_skb, *p_sva, *p_svb, *p_yka, *p_ykb, *p_yva, *p_yvb, *p_tmp;
    cudaGetSymbolAddress(&p_ska, g_sk_a);
    cudaGetSymbolAddress(&p_skb, g_sk_b);
    cudaGetSymbolAddress(&p_sva, g_sv_a);
    cudaGetSymbolAddress(&p_svb, g_sv_b);
    cudaGetSymbolAddress(&p_yka, g_yk_a);
    cudaGetSymbolAddress(&p_ykb, g_yk_b);
    cudaGetSymbolAddress(&p_yva, g_yv_a);
    cudaGetSymbolAddress(&p_yvb, g_yv_b);
    cudaGetSymbolAddress(&p_tmp, g_cub_temp);

    k_zero<<<(NWIN * PADC + 1023) / 1024, 1024>>>();
    k_score<<<(NBOX + 255) / 256, 256>>>(scores, deltas);

    size_t tb = sizeof(g_cub_temp);
    cub::DeviceRadixSort::SortPairs(p_tmp, tb,
        (const unsigned*)p_ska, (unsigned*)p_skb,
        (const unsigned*)p_sva, (unsigned*)p_svb, NBOX);

    k_props<<<(KTOP + 255) / 256, 256>>>(deltas);

    tb = sizeof(g_cub_temp);
    cub::DeviceRadixSort::SortPairs(p_tmp, tb,
        (const unsigned*)p_yka, (unsigned*)p_ykb,
        (const unsigned*)p_yva, (unsigned*)p_yvb, KTOP);

    k_prep<<<(PADK + 255) / 256, 256>>>();
    k_pairs<<<NWIN, 256>>>();
    k_serial<<<1, 1024>>>(out);
}